// round 3
// baseline (speedup 1.0000x reference)
#include <cuda_runtime.h>
#include <math.h>

#define BB 128
#define SS 26
#define AA 5
#define PP 3380   /* 26*26*5 */
#define MM 30
#define DD 25
#define TILE 256
#define NTILES 14 /* ceil(3380/256) */
#define CWF 16.0f

#define N_PRED (BB * PP * DD)  /* 10,816,000 */
#define N_TGT  (BB * MM * 5)   /* 19,200 */
#define N_ANC  (AA * 2)        /* 10 */

__device__ unsigned long long g_argmax[BB * MM];
__device__ double g_conf;

__device__ __forceinline__ float sigf(float x) {
    return 1.0f / (1.0f + __expf(-x));
}

// order-preserving float -> u32 (monotone for all non-NaN floats)
__device__ __forceinline__ unsigned int okey(float f) {
    unsigned int u = __float_as_uint(f);
    return (u & 0x80000000u) ? ~u : (u | 0x80000000u);
}

__global__ void k_init() {
    int i = blockIdx.x * blockDim.x + threadIdx.x;
    if (i < BB * MM) g_argmax[i] = 0ull;
    if (i == 0) g_conf = 0.0;
}

__global__ __launch_bounds__(TILE) void k_main(
    const float* __restrict__ pred,
    const float* __restrict__ tgt,
    const float* __restrict__ anc)
{
    __shared__ float4 sBox[TILE];
    __shared__ float  sArea[TILE];
    __shared__ unsigned long long sMerge[MM];
    __shared__ float sConf[TILE / 32];

    const int tid  = threadIdx.x;
    const int lane = tid & 31;
    const int warp = tid >> 5;
    const int b    = blockIdx.x / NTILES;
    const int tile = blockIdx.x % NTILES;
    const int pbase = tile * TILE;
    const int p = pbase + tid;

    const float INF = __int_as_float(0x7f800000);

    // ---- GT box per lane (lane plays role of annotation m) ----
    float gx1, gx2, gy1, gy2, s;
    {
        bool v = false;
        float x1 = 0.f, y1 = 0.f, w = 0.f, h = 0.f;
        if (lane < MM) {
            const float* t = tgt + ((size_t)b * MM + lane) * 5;
            x1 = t[0]; y1 = t[1]; w = t[2]; h = t[3];
            v = (t[4] == 1.0f);
        }
        float gxc = x1 + 0.5f * w;
        float gyc = y1 + 0.5f * h;
        float gw  = w - x1;      // faithful to source
        float gh  = h * y1;      // faithful to source
        gx1 = gxc - 0.5f * gw; gx2 = gxc + 0.5f * gw;
        gy1 = gyc - 0.5f * gh; gy2 = gyc + 0.5f * gh;
        s = gw * gh + 1e-9f;     // area_g + eps
        if (!v) {
            // invalid / out-of-range lane: force IoU == 0 for every pred
            gx1 = INF; gx2 = -INF; gy1 = INF; gy2 = -INF;
            s = 1e-9f;
        }
    }

    // ---- decode one prediction per thread into SMEM ----
    float t1 = 0.f, t2 = 0.f;   // conf-loss terms for this thread's p
    if (p < PP) {
        const float* pv = pred + ((size_t)b * PP + p) * DD;
        float v0 = pv[0], v1 = pv[1], v2 = pv[2], v3 = pv[3], v4 = pv[4];
        int a   = p % AA;
        int rem = p / AA;
        int jc  = rem % SS;      // column (gx)
        int ir  = rem / SS;      // row    (gy)
        float sx = sigf(v0), sy = sigf(v1);
        float bw = __expf(0.5f * sigf(v2)) * anc[2 * a]     * CWF;
        float bh = __expf(0.5f * sigf(v3)) * anc[2 * a + 1] * CWF;
        float bx = (sx + (float)jc) * CWF;
        float by = (sy + (float)ir) * CWF;
        sBox[tid]  = make_float4(bx - 0.5f * bw, bx + 0.5f * bw,
                                 by - 0.5f * bh, by + 0.5f * bh);
        sArea[tid] = bw * bh;
        float pc = sigf(v4);
        t1 = (pc - 1.f) * (pc - 1.f); // obj  term
        t2 = 0.5f * pc * pc;          // noobj term
    } else {
        sBox[tid]  = make_float4(0.f, 0.f, 0.f, 0.f);
        sArea[tid] = 0.f;
    }
    if (tid < MM) sMerge[tid] = 0ull;
    __syncthreads();

    // ---- IoU sweep: warp handles 32 preds, lane = m ----
    float best = -INF;
    int   bestp = 0;
    bool  myobj = false;
    const int pw = pbase + warp * 32;
    int jcnt = PP - pw;
    if (jcnt > 32) jcnt = 32;
    if (jcnt < 0)  jcnt = 0;

    #pragma unroll 4
    for (int j = 0; j < jcnt; ++j) {
        float4 bb = sBox[warp * 32 + j];
        float  ap = sArea[warp * 32 + j];
        float dx = fmaxf(fminf(gx2, bb.y) - fmaxf(gx1, bb.x), 0.f);
        float dy = fmaxf(fminf(gy2, bb.w) - fmaxf(gy1, bb.z), 0.f);
        float inter = dx * dy;
        float den = s + ap - inter;           // area_g + eps + area_p - inter
        float iou = __fdividef(inter, den);
        // canonicalize -0.0 -> +0.0 so argmax tie-break across warps matches
        // jnp.argmax (-0.0 == +0.0, first index wins)
        if (__float_as_uint(iou) == 0x80000000u) iou = 0.0f;
        unsigned msk = __ballot_sync(0xFFFFFFFFu, iou > 0.6f);
        if (lane == j) myobj = (msk != 0u);
        if (iou > best) { best = iou; bestp = pw + j; }
    }

    // ---- merge per-(b,m) argmax: block-level then global ----
    if (lane < MM) {
        unsigned long long pk =
            ((unsigned long long)okey(best) << 32) | (unsigned int)(~bestp);
        atomicMax(&sMerge[lane], pk);
    }
    __syncthreads();
    if (tid < MM) atomicMax(&g_argmax[b * MM + tid], sMerge[tid]);

    // ---- conf loss reduce ----
    float acc = (p < PP) ? (myobj ? t1 : t2) : 0.f;
    #pragma unroll
    for (int o = 16; o; o >>= 1) acc += __shfl_down_sync(0xFFFFFFFFu, acc, o);
    if (lane == 0) sConf[warp] = acc;
    __syncthreads();
    if (warp == 0) {
        float v = (lane < TILE / 32) ? sConf[lane] : 0.f;
        #pragma unroll
        for (int o = 4; o; o >>= 1) v += __shfl_down_sync(0xFFFFFFFFu, v, o);
        if (lane == 0) atomicAdd(&g_conf, (double)v);
    }
}

__global__ void k_post(const float* __restrict__ pred,
                       const float* __restrict__ tgt,
                       const float* __restrict__ anc,
                       float* __restrict__ out)
{
    __shared__ double sred[BB];
    const int b = threadIdx.x;

    int   idxs[MM];
    float vx[MM], vy[MM], vw[MM], vh[MM];
    int n = 0;
    for (int m = 0; m < MM; ++m) {
        const float* t = tgt + ((size_t)b * MM + m) * 5;
        if (t[4] == 1.0f) {
            unsigned long long pk = g_argmax[b * MM + m];
            int p = (int)(~(unsigned int)pk);
            int ra = p % AA;
            int rw = (p / AA) % SS;
            int rh = p / (AA * SS);
            float gxc = t[0] + 0.5f * t[2];
            float gyc = t[1] + 0.5f * t[3];
            idxs[n] = p;
            vx[n] = (gxc - (float)rw * CWF) / CWF;
            vy[n] = (gyc - (float)rh * CWF) / CWF;
            vw[n] = logf((t[2] / CWF) / anc[2 * ra]);
            vh[n] = logf((t[3] / CWF) / anc[2 * ra + 1]);
            n++;
        }
    }

    // scatter with .set semantics: duplicate target index -> last write wins
    double lsum = 0.0;
    for (int j = 0; j < n; ++j) {
        bool last = true;
        for (int k = j + 1; k < n; ++k)
            if (idxs[k] == idxs[j]) { last = false; break; }
        if (!last) continue;
        const float* pv = pred + ((size_t)b * PP + idxs[j]) * DD;
        float p0 = 1.f / (1.f + expf(-pv[0]));
        float p1 = 1.f / (1.f + expf(-pv[1]));
        float p2 = 0.5f / (1.f + expf(-pv[2]));
        float p3 = 0.5f / (1.f + expf(-pv[3]));
        float d0 = p0 - vx[j], d1 = p1 - vy[j];
        float d2 = p2 - vw[j], d3 = p3 - vh[j];
        lsum += (double)(d0 * d0 + d1 * d1 + d2 * d2 + d3 * d3);
    }
    sred[b] = lsum;
    __syncthreads();
    for (int o = BB / 2; o; o >>= 1) {
        if (b < o) sred[b] += sred[b + o];
        __syncthreads();
    }
    if (b == 0) {
        double loc  = 5.0 * sred[0] / (double)BB;
        double conf = g_conf / (double)BB;
        out[0] = (float)(loc + conf);
        out[1] = (float)loc;
        out[2] = (float)conf;
    }
}

extern "C" void kernel_launch(void* const* d_in, const int* in_sizes, int n_in,
                              void* d_out, int out_size)
{
    // Robust input dispatch: identify tensors by unique element counts
    // (pred = 10,816,000; target = 19,200; anchors = 10), independent of order.
    const float* pred = 0;
    const float* tgt  = 0;
    const float* anc  = 0;
    for (int i = 0; i < n_in; ++i) {
        if (in_sizes[i] == N_PRED)      pred = (const float*)d_in[i];
        else if (in_sizes[i] == N_TGT)  tgt  = (const float*)d_in[i];
        else if (in_sizes[i] == N_ANC)  anc  = (const float*)d_in[i];
    }
    float* out = (float*)d_out;

    k_init<<<(BB * MM + 255) / 256, 256>>>();
    k_main<<<BB * NTILES, TILE>>>(pred, tgt, anc);
    k_post<<<1, BB>>>(pred, tgt, anc, out);
}

// round 4
// speedup vs baseline: 4.2281x; 4.2281x over previous
#include <cuda_runtime.h>
#include <math.h>

#define BB 128
#define SS 26
#define AA 5
#define PP 3380   /* 26*26*5 */
#define MM 30
#define TILE 256
#define NTILES 14 /* ceil(3380/256) */
#define CWF 16.0f

#define N_PRED 10816000
#define N_TGT  19200
#define N_ANC  10

__device__ unsigned long long g_part[BB * NTILES * MM];
__device__ float  g_confp[BB * NTILES];
__device__ double g_bloc[BB];
__device__ double g_bconf[BB];
__device__ int    g_ctr;   // zero-init at module load; reset by last block each run

__device__ __forceinline__ float sigf(float x) {
    return 1.0f / (1.0f + __expf(-x));
}
// order-preserving float -> u32 (monotone for all non-NaN floats)
__device__ __forceinline__ unsigned int okey(float f) {
    unsigned int u = __float_as_uint(f);
    return (u & 0x80000000u) ? ~u : (u | 0x80000000u);
}

__global__ __launch_bounds__(TILE) void k_main(
    const float* __restrict__ pred,
    const float* __restrict__ tgt,
    const float* __restrict__ anc)
{
    __shared__ float  sChunk[TILE * 25];   // 25.6 KB staged pred records
    __shared__ float4 sBox[TILE];
    __shared__ float  sArea[TILE];
    __shared__ float  sTgt[MM * 5];
    __shared__ unsigned long long sMerge[MM];
    __shared__ float  sConf[TILE / 32];

    const int tid  = threadIdx.x;
    const int lane = tid & 31;
    const int warp = tid >> 5;
    const int b    = blockIdx.x / NTILES;
    const int tile = blockIdx.x % NTILES;
    const int nrec = min(TILE, PP - tile * TILE);   // 256, or 52 on last tile
    const float INF = __int_as_float(0x7f800000);

    // ---- coalesced staging: pred chunk (contiguous) + targets ----
    {
        const float4* g4 = (const float4*)(pred + ((size_t)b * PP + tile * TILE) * 25);
        int n4 = (nrec * 25) >> 2;   // 1600 or 325 (both exact)
        for (int i = tid; i < n4; i += TILE) ((float4*)sChunk)[i] = g4[i];
        if (tid < MM * 5) sTgt[tid] = tgt[b * MM * 5 + tid];
        if (tid < MM) sMerge[tid] = 0ull;
    }
    __syncthreads();

    // ---- decode one prediction per thread (SMEM stride-25: conflict-free) ----
    float t1 = 0.f, t2 = 0.f;
    if (tid < nrec) {
        float v0 = sChunk[tid * 25 + 0], v1 = sChunk[tid * 25 + 1];
        float v2 = sChunk[tid * 25 + 2], v3 = sChunk[tid * 25 + 3];
        float v4 = sChunk[tid * 25 + 4];
        int p   = tile * TILE + tid;
        int a   = p % AA;
        int rem = p / AA;
        int jc  = rem % SS;
        int ir  = rem / SS;
        float bw = __expf(0.5f * sigf(v2)) * __ldg(&anc[2 * a])     * CWF;
        float bh = __expf(0.5f * sigf(v3)) * __ldg(&anc[2 * a + 1]) * CWF;
        float bx = (sigf(v0) + (float)jc) * CWF;
        float by = (sigf(v1) + (float)ir) * CWF;
        sBox[tid]  = make_float4(bx - 0.5f * bw, bx + 0.5f * bw,
                                 by - 0.5f * bh, by + 0.5f * bh);
        sArea[tid] = bw * bh;
        float pc = sigf(v4);
        t1 = (pc - 1.f) * (pc - 1.f);
        t2 = 0.5f * pc * pc;
    } else {
        sBox[tid]  = make_float4(0.f, 0.f, 0.f, 0.f);
        sArea[tid] = 0.f;
    }

    // ---- GT box per lane (lane = annotation m) ----
    float gx1, gx2, gy1, gy2, s;
    {
        bool v = false;
        float x1 = 0.f, y1 = 0.f, w = 0.f, h = 0.f;
        if (lane < MM) {
            x1 = sTgt[lane * 5 + 0]; y1 = sTgt[lane * 5 + 1];
            w  = sTgt[lane * 5 + 2]; h  = sTgt[lane * 5 + 3];
            v  = (sTgt[lane * 5 + 4] == 1.0f);
        }
        float gxc = x1 + 0.5f * w;
        float gyc = y1 + 0.5f * h;
        float gw  = w - x1;      // faithful to source
        float gh  = h * y1;      // faithful to source
        gx1 = gxc - 0.5f * gw; gx2 = gxc + 0.5f * gw;
        gy1 = gyc - 0.5f * gh; gy2 = gyc + 0.5f * gh;
        s = gw * gh + 1e-9f;
        if (!v) { gx1 = INF; gx2 = -INF; gy1 = INF; gy2 = -INF; s = 1e-9f; }
    }
    __syncthreads();

    // ---- IoU sweep: warp handles 32 preds, lane = m; mask bit j = (iou>thr) ----
    unsigned mask = 0;
    float best = -INF;
    int   bestp = 0;
    const int base = warp * 32;
    const int pw = tile * TILE + base;
    int jcnt = nrec - base;
    if (jcnt > 32) jcnt = 32;
    if (jcnt < 0)  jcnt = 0;

    #pragma unroll 8
    for (int j = 0; j < jcnt; ++j) {
        float4 bx = sBox[base + j];
        float  ap = sArea[base + j];
        float dx = fmaxf(fminf(gx2, bx.y) - fmaxf(gx1, bx.x), 0.f);
        float dy = fmaxf(fminf(gy2, bx.w) - fmaxf(gy1, bx.z), 0.f);
        float inter = dx * dy;
        float iou = __fdividef(inter, s + ap - inter);
        // canonicalize -0.0 -> +0.0 (argmax tie-break parity with jnp.argmax)
        if (__float_as_uint(iou) == 0x80000000u) iou = 0.0f;
        if (iou > 0.6f) mask |= (1u << j);
        if (iou > best) { best = iou; bestp = pw + j; }
    }
    unsigned objw = __reduce_or_sync(0xFFFFFFFFu, mask);  // bit j = obj(pred pw+j)
    bool myobj = (objw >> lane) & 1u;                     // my own pred is pw+lane

    if (lane < MM) {
        unsigned long long pk =
            ((unsigned long long)okey(best) << 32) | (unsigned int)(~bestp);
        atomicMax(&sMerge[lane], pk);
    }

    // ---- conf partial reduce (fixed order -> deterministic) ----
    float acc = (tid < nrec) ? (myobj ? t1 : t2) : 0.f;
    #pragma unroll
    for (int o = 16; o; o >>= 1) acc += __shfl_down_sync(0xFFFFFFFFu, acc, o);
    if (lane == 0) sConf[warp] = acc;
    __syncthreads();
    if (tid < MM) g_part[(size_t)blockIdx.x * MM + tid] = sMerge[tid];
    if (warp == 0) {
        float v = (lane < TILE / 32) ? sConf[lane] : 0.f;
        #pragma unroll
        for (int o = 4; o; o >>= 1) v += __shfl_down_sync(0xFFFFFFFFu, v, o);
        if (lane == 0) g_confp[blockIdx.x] = v;
    }
}

__global__ __launch_bounds__(32) void k_post(
    const float* __restrict__ pred,
    const float* __restrict__ tgt,
    const float* __restrict__ anc,
    float* __restrict__ out)
{
    const int b    = blockIdx.x;
    const int lane = threadIdx.x;

    // reduce argmax over tiles for my annotation m = lane
    unsigned long long best = 0ull;
    float x1 = 0.f, y1 = 0.f, w = 0.f, h = 0.f;
    bool valid = false;
    if (lane < MM) {
        const float* t = tgt + ((size_t)b * MM + lane) * 5;
        x1 = t[0]; y1 = t[1]; w = t[2]; h = t[3];
        valid = (t[4] == 1.0f);
        #pragma unroll
        for (int k = 0; k < NTILES; ++k) {
            unsigned long long v = g_part[((size_t)b * NTILES + k) * MM + lane];
            if (v > best) best = v;
        }
    }
    int p = valid ? (int)(~(unsigned int)best) : (0x10000 + lane);

    // scatter .set semantics: same flat index -> highest m (last write) wins
    unsigned grp = __match_any_sync(0xFFFFFFFFu, p);
    bool writer = valid && (lane == 31 - __clz(grp));

    float term = 0.f;
    if (writer) {
        int ra = p % AA, rw = (p / AA) % SS, rh = p / (AA * SS);
        float gxc = x1 + 0.5f * w;
        float gyc = y1 + 0.5f * h;
        float vx = (gxc - (float)rw * CWF) / CWF;
        float vy = (gyc - (float)rh * CWF) / CWF;
        float vw_ = logf((w / CWF) / __ldg(&anc[2 * ra]));
        float vh_ = logf((h / CWF) / __ldg(&anc[2 * ra + 1]));
        const float* pv = pred + ((size_t)b * PP + p) * 25;
        float p0 = 1.f   / (1.f + expf(-pv[0]));
        float p1 = 1.f   / (1.f + expf(-pv[1]));
        float p2 = 0.5f  / (1.f + expf(-pv[2]));
        float p3 = 0.5f  / (1.f + expf(-pv[3]));
        float d0 = p0 - vx, d1 = p1 - vy, d2 = p2 - vw_, d3 = p3 - vh_;
        term = d0 * d0 + d1 * d1 + d2 * d2 + d3 * d3;
    }
    float cpart = (lane < NTILES) ? g_confp[b * NTILES + lane] : 0.f;
    #pragma unroll
    for (int o = 16; o; o >>= 1) {
        term  += __shfl_down_sync(0xFFFFFFFFu, term,  o);
        cpart += __shfl_down_sync(0xFFFFFFFFu, cpart, o);
    }

    int done = 0;
    if (lane == 0) {
        g_bloc[b]  = (double)term;
        g_bconf[b] = (double)cpart;
        __threadfence();
        done = atomicAdd(&g_ctr, 1);
    }
    done = __shfl_sync(0xFFFFFFFFu, done, 0);

    if (done == BB - 1) {   // last block finalizes (fixed-order -> deterministic)
        double l = 0.0, c = 0.0;
        for (int i = lane; i < BB; i += 32) {
            l += __ldcg(&g_bloc[i]);
            c += __ldcg(&g_bconf[i]);
        }
        #pragma unroll
        for (int o = 16; o; o >>= 1) {
            l += __shfl_down_sync(0xFFFFFFFFu, l, o);
            c += __shfl_down_sync(0xFFFFFFFFu, c, o);
        }
        if (lane == 0) {
            double loc  = 5.0 * l / (double)BB;
            double conf = c / (double)BB;
            out[0] = (float)(loc + conf);
            out[1] = (float)loc;
            out[2] = (float)conf;
            g_ctr = 0;
        }
    }
}

extern "C" void kernel_launch(void* const* d_in, const int* in_sizes, int n_in,
                              void* d_out, int out_size)
{
    const float* pred = 0;
    const float* tgt  = 0;
    const float* anc  = 0;
    for (int i = 0; i < n_in; ++i) {
        if (in_sizes[i] == N_PRED)      pred = (const float*)d_in[i];
        else if (in_sizes[i] == N_TGT)  tgt  = (const float*)d_in[i];
        else if (in_sizes[i] == N_ANC)  anc  = (const float*)d_in[i];
    }
    float* out = (float*)d_out;

    k_main<<<BB * NTILES, TILE>>>(pred, tgt, anc);
    k_post<<<BB, 32>>>(pred, tgt, anc, out);
}

// round 5
// speedup vs baseline: 4.8586x; 1.1491x over previous
#include <cuda_runtime.h>
#include <math.h>

#define BB 128
#define SS 26
#define AA 5
#define PP 3380   /* 26*26*5 */
#define MM 30
#define TILE 256
#define NTILES 14 /* ceil(3380/256) */
#define CWF 16.0f

#define N_PRED 10816000
#define N_TGT  19200
#define N_ANC  10

__device__ unsigned long long g_part[BB * NTILES * MM];
__device__ float  g_confp[BB * NTILES];
__device__ double g_bloc[BB];
__device__ double g_bconf[BB];
__device__ int    g_bctr[BB];  // zero at load; reset each run by batch-last block
__device__ int    g_gctr;      // zero at load; reset each run by global-last block

__device__ __forceinline__ float sigf(float x) {
    return 1.0f / (1.0f + __expf(-x));
}
// order-preserving float -> u32 (monotone for all non-NaN floats)
__device__ __forceinline__ unsigned int okey(float f) {
    unsigned int u = __float_as_uint(f);
    return (u & 0x80000000u) ? ~u : (u | 0x80000000u);
}

__global__ __launch_bounds__(TILE) void k_main(
    const float* __restrict__ pred,
    const float* __restrict__ tgt,
    const float* __restrict__ anc,
    float* __restrict__ out)
{
    __shared__ float  sChunk[TILE * 25];   // 25.6 KB staged pred records
    __shared__ float4 sBox[TILE];
    __shared__ float  sArea[TILE];
    __shared__ float  sTgt[MM * 5];
    __shared__ unsigned long long sMerge[MM];
    __shared__ float  sConf[TILE / 32];
    __shared__ int    sIsLast;

    const int tid  = threadIdx.x;
    const int lane = tid & 31;
    const int warp = tid >> 5;
    const int b    = blockIdx.x / NTILES;
    const int tile = blockIdx.x % NTILES;
    const int nrec = min(TILE, PP - tile * TILE);   // 256, or 52 on last tile
    const float INF = __int_as_float(0x7f800000);

    // ---- coalesced staging ----
    {
        const float4* g4 = (const float4*)(pred + ((size_t)b * PP + tile * TILE) * 25);
        int n4 = (nrec * 25) >> 2;   // 1600 or 325 (both exact)
        for (int i = tid; i < n4; i += TILE) ((float4*)sChunk)[i] = g4[i];
        if (tid < MM * 5) sTgt[tid] = tgt[b * MM * 5 + tid];
        if (tid < MM) sMerge[tid] = 0ull;
    }
    __syncthreads();

    // ---- decode one prediction per thread (stride-25 SMEM: conflict-free) ----
    float t1 = 0.f, t2 = 0.f;
    if (tid < nrec) {
        float v0 = sChunk[tid * 25 + 0], v1 = sChunk[tid * 25 + 1];
        float v2 = sChunk[tid * 25 + 2], v3 = sChunk[tid * 25 + 3];
        float v4 = sChunk[tid * 25 + 4];
        int p   = tile * TILE + tid;
        int a   = p % AA;
        int rem = p / AA;
        int jc  = rem % SS;
        int ir  = rem / SS;
        float bw = __expf(0.5f * sigf(v2)) * __ldg(&anc[2 * a])     * CWF;
        float bh = __expf(0.5f * sigf(v3)) * __ldg(&anc[2 * a + 1]) * CWF;
        float bx = (sigf(v0) + (float)jc) * CWF;
        float by = (sigf(v1) + (float)ir) * CWF;
        sBox[tid]  = make_float4(bx - 0.5f * bw, bx + 0.5f * bw,
                                 by - 0.5f * bh, by + 0.5f * bh);
        sArea[tid] = bw * bh;
        float pc = sigf(v4);
        t1 = (pc - 1.f) * (pc - 1.f);
        t2 = 0.5f * pc * pc;
    } else {
        sBox[tid]  = make_float4(0.f, 0.f, 0.f, 0.f);
        sArea[tid] = 0.f;
    }

    // ---- GT box per lane (lane = annotation m) ----
    float gx1, gx2, gy1, gy2, s;
    {
        bool v = false;
        float x1 = 0.f, y1 = 0.f, w = 0.f, h = 0.f;
        if (lane < MM) {
            x1 = sTgt[lane * 5 + 0]; y1 = sTgt[lane * 5 + 1];
            w  = sTgt[lane * 5 + 2]; h  = sTgt[lane * 5 + 3];
            v  = (sTgt[lane * 5 + 4] == 1.0f);
        }
        float gxc = x1 + 0.5f * w;
        float gyc = y1 + 0.5f * h;
        float gw  = w - x1;      // faithful to source
        float gh  = h * y1;      // faithful to source
        gx1 = gxc - 0.5f * gw; gx2 = gxc + 0.5f * gw;
        gy1 = gyc - 0.5f * gh; gy2 = gyc + 0.5f * gh;
        s = gw * gh + 1e-9f;
        if (!v) { gx1 = INF; gx2 = -INF; gy1 = INF; gy2 = -INF; s = 1e-9f; }
    }
    __syncthreads();

    // ---- IoU sweep: warp handles its 32 preds, lane = m ----
    // Within a lane, IEEE '>' keeps first index on +0/-0 ties (argmax parity);
    // -0.0 is canonicalized once at key-pack time for cross-warp merge.
    unsigned mask = 0;
    float best = -INF;
    int   bestj = 0;
    const int base = warp * 32;
    const int pw = tile * TILE + base;
    int jcnt = nrec - base;
    if (jcnt > 32) jcnt = 32;
    if (jcnt < 0)  jcnt = 0;

    if (jcnt == 32) {
        #pragma unroll
        for (int j = 0; j < 32; ++j) {
            float4 bx = sBox[base + j];
            float  ap = sArea[base + j];
            float dx = fmaxf(fminf(gx2, bx.y) - fmaxf(gx1, bx.x), 0.f);
            float dy = fmaxf(fminf(gy2, bx.w) - fmaxf(gy1, bx.z), 0.f);
            float inter = dx * dy;
            float iou = __fdividef(inter, s + ap - inter);
            if (iou > 0.6f) mask |= (1u << j);
            if (iou > best) { best = iou; bestj = j; }
        }
    } else {
        for (int j = 0; j < jcnt; ++j) {
            float4 bx = sBox[base + j];
            float  ap = sArea[base + j];
            float dx = fmaxf(fminf(gx2, bx.y) - fmaxf(gx1, bx.x), 0.f);
            float dy = fmaxf(fminf(gy2, bx.w) - fmaxf(gy1, bx.z), 0.f);
            float inter = dx * dy;
            float iou = __fdividef(inter, s + ap - inter);
            if (iou > 0.6f) mask |= (1u << j);
            if (iou > best) { best = iou; bestj = j; }
        }
    }
    unsigned objw = __reduce_or_sync(0xFFFFFFFFu, mask);  // bit j = obj(pred pw+j)
    bool myobj = (objw >> lane) & 1u;

    if (lane < MM) {
        if (__float_as_uint(best) == 0x80000000u) best = 0.0f;  // -0 -> +0
        unsigned long long pk =
            ((unsigned long long)okey(best) << 32) | (unsigned int)(~(pw + bestj));
        atomicMax(&sMerge[lane], pk);
    }

    // ---- conf partial reduce (fixed order -> deterministic) ----
    float acc = (tid < nrec) ? (myobj ? t1 : t2) : 0.f;
    #pragma unroll
    for (int o = 16; o; o >>= 1) acc += __shfl_down_sync(0xFFFFFFFFu, acc, o);
    if (lane == 0) sConf[warp] = acc;
    __syncthreads();

    // ---- warp 0 publishes this tile's results, then maybe runs the tail ----
    if (warp != 0) return;

    if (lane < MM) g_part[(size_t)blockIdx.x * MM + lane] = sMerge[lane];
    {
        float v = (lane < TILE / 32) ? sConf[lane] : 0.f;
        #pragma unroll
        for (int o = 4; o; o >>= 1) v += __shfl_down_sync(0xFFFFFFFFu, v, o);
        if (lane == 0) g_confp[blockIdx.x] = v;
    }
    __threadfence();
    __syncwarp();
    int cnt = 0;
    if (lane == 0) cnt = atomicAdd(&g_bctr[b], 1);
    cnt = __shfl_sync(0xFFFFFFFFu, cnt, 0);
    if (cnt != NTILES - 1) return;

    // ===== per-batch post (this is the 14th/last tile-block of batch b) =====
    unsigned long long bk = 0ull;
    float x1 = 0.f, y1 = 0.f, w = 0.f, h = 0.f;
    bool valid = false;
    if (lane < MM) {
        x1 = sTgt[lane * 5 + 0]; y1 = sTgt[lane * 5 + 1];
        w  = sTgt[lane * 5 + 2]; h  = sTgt[lane * 5 + 3];
        valid = (sTgt[lane * 5 + 4] == 1.0f);
        #pragma unroll
        for (int k = 0; k < NTILES; ++k) {
            unsigned long long v = __ldcg(&g_part[((size_t)b * NTILES + k) * MM + lane]);
            if (v > bk) bk = v;
        }
    }
    int p = valid ? (int)(~(unsigned int)bk) : (0x10000 + lane);

    // scatter .set semantics: same flat index -> highest m (last write) wins
    unsigned grp = __match_any_sync(0xFFFFFFFFu, p);
    bool writer = valid && (lane == 31 - __clz(grp));

    float term = 0.f;
    if (writer) {
        int ra = p % AA, rw = (p / AA) % SS, rh = p / (AA * SS);
        float gxc = x1 + 0.5f * w;
        float gyc = y1 + 0.5f * h;
        float vx = (gxc - (float)rw * CWF) / CWF;
        float vy = (gyc - (float)rh * CWF) / CWF;
        float vw_ = logf((w / CWF) / __ldg(&anc[2 * ra]));
        float vh_ = logf((h / CWF) / __ldg(&anc[2 * ra + 1]));
        const float* pv = pred + ((size_t)b * PP + p) * 25;
        float p0 = 1.f   / (1.f + expf(-pv[0]));
        float p1 = 1.f   / (1.f + expf(-pv[1]));
        float p2 = 0.5f  / (1.f + expf(-pv[2]));
        float p3 = 0.5f  / (1.f + expf(-pv[3]));
        float d0 = p0 - vx, d1 = p1 - vy, d2 = p2 - vw_, d3 = p3 - vh_;
        term = d0 * d0 + d1 * d1 + d2 * d2 + d3 * d3;
    }
    float cpart = (lane < NTILES) ? __ldcg(&g_confp[b * NTILES + lane]) : 0.f;
    #pragma unroll
    for (int o = 16; o; o >>= 1) {
        term  += __shfl_down_sync(0xFFFFFFFFu, term,  o);
        cpart += __shfl_down_sync(0xFFFFFFFFu, cpart, o);
    }

    int done = 0;
    if (lane == 0) {
        g_bctr[b] = 0;                 // reset for next launch
        g_bloc[b]  = (double)term;
        g_bconf[b] = (double)cpart;
        __threadfence();
        done = atomicAdd(&g_gctr, 1);
    }
    done = __shfl_sync(0xFFFFFFFFu, done, 0);
    if (done != BB - 1) return;

    // ===== global finalize (deterministic fixed-order reduce) =====
    double l = 0.0, c = 0.0;
    for (int i = lane; i < BB; i += 32) {
        l += __ldcg(&g_bloc[i]);
        c += __ldcg(&g_bconf[i]);
    }
    #pragma unroll
    for (int o = 16; o; o >>= 1) {
        l += __shfl_down_sync(0xFFFFFFFFu, l, o);
        c += __shfl_down_sync(0xFFFFFFFFu, c, o);
    }
    if (lane == 0) {
        double loc  = 5.0 * l / (double)BB;
        double conf = c / (double)BB;
        out[0] = (float)(loc + conf);
        out[1] = (float)loc;
        out[2] = (float)conf;
        g_gctr = 0;                    // reset for next launch
    }
}

extern "C" void kernel_launch(void* const* d_in, const int* in_sizes, int n_in,
                              void* d_out, int out_size)
{
    const float* pred = 0;
    const float* tgt  = 0;
    const float* anc  = 0;
    for (int i = 0; i < n_in; ++i) {
        if (in_sizes[i] == N_PRED)      pred = (const float*)d_in[i];
        else if (in_sizes[i] == N_TGT)  tgt  = (const float*)d_in[i];
        else if (in_sizes[i] == N_ANC)  anc  = (const float*)d_in[i];
    }
    float* out = (float*)d_out;

    k_main<<<BB * NTILES, TILE>>>(pred, tgt, anc, out);
}

// round 7
// speedup vs baseline: 5.1825x; 1.0667x over previous
#include <cuda_runtime.h>
#include <math.h>

#define BB 128
#define SS 26
#define AA 5
#define PP 3380   /* 26*26*5 */
#define MM 30
#define TILE 256
#define NTILES 14 /* ceil(3380/256) */
#define CWF 16.0f

#define N_PRED 10816000
#define N_TGT  19200
#define N_ANC  10

__device__ unsigned long long g_part[BB * NTILES * MM];
__device__ float  g_confp[BB * NTILES];
__device__ double g_bloc[BB];
__device__ double g_bconf[BB];
__device__ int    g_bctr[BB];  // zero at load; reset each run by batch-last block
__device__ int    g_gctr;      // zero at load; reset each run by global-last block

__device__ __forceinline__ float sigf(float x) {
    return 1.0f / (1.0f + __expf(-x));
}
// order-preserving float -> u32 (monotone for all non-NaN floats)
__device__ __forceinline__ unsigned int okey(float f) {
    unsigned int u = __float_as_uint(f);
    return (u & 0x80000000u) ? ~u : (u | 0x80000000u);
}

__global__ __launch_bounds__(TILE) void k_main(
    const float* __restrict__ pred,
    const float* __restrict__ tgt,
    const float* __restrict__ anc,
    float* __restrict__ out)
{
    __shared__ float4 sBox[TILE];          // (x2, y2, x1, y1)
    __shared__ float  sArea[TILE];
    __shared__ float  sTgt[MM * 5];
    __shared__ unsigned long long sMerge[MM];
    __shared__ float  sConf[TILE / 32];

    const int tid  = threadIdx.x;
    const int lane = tid & 31;
    const int warp = tid >> 5;
    const int b    = blockIdx.x / NTILES;
    const int tile = blockIdx.x % NTILES;
    const int nrec = min(TILE, PP - tile * TILE);   // 256, or 52 on last tile
    const float INF = __int_as_float(0x7f800000);

    if (tid < MM * 5) sTgt[tid] = tgt[b * MM * 5 + tid];
    if (tid < MM) sMerge[tid] = 0ull;

    // ---- decode one prediction per thread (direct scalar LDG, one-time) ----
    float t1 = 0.f, t2 = 0.f;
    if (tid < nrec) {
        const int p = tile * TILE + tid;
        const float* pv = pred + ((size_t)b * PP + p) * 25;
        float v0 = __ldg(pv + 0), v1 = __ldg(pv + 1), v2 = __ldg(pv + 2);
        float v3 = __ldg(pv + 3), v4 = __ldg(pv + 4);
        int a   = p % AA;
        int rem = p / AA;
        int jc  = rem % SS;
        int ir  = rem / SS;
        float bw = __expf(0.5f * sigf(v2)) * __ldg(&anc[2 * a])     * CWF;
        float bh = __expf(0.5f * sigf(v3)) * __ldg(&anc[2 * a + 1]) * CWF;
        float bx = (sigf(v0) + (float)jc) * CWF;
        float by = (sigf(v1) + (float)ir) * CWF;
        float hw = 0.5f * bw, hh = 0.5f * bh;
        sBox[tid]  = make_float4(bx + hw, by + hh, bx - hw, by - hh);
        sArea[tid] = bw * bh;
        float pc = sigf(v4);
        t1 = (pc - 1.f) * (pc - 1.f);
        t2 = 0.5f * pc * pc;
    }
    __syncthreads();

    // ---- GT box per lane (lane = annotation m) ----
    float gx1, gx2, gy1, gy2, s;
    {
        bool v = false;
        float x1 = 0.f, y1 = 0.f, w = 0.f, h = 0.f;
        if (lane < MM) {
            x1 = sTgt[lane * 5 + 0]; y1 = sTgt[lane * 5 + 1];
            w  = sTgt[lane * 5 + 2]; h  = sTgt[lane * 5 + 3];
            v  = (sTgt[lane * 5 + 4] == 1.0f);
        }
        float gxc = x1 + 0.5f * w;
        float gyc = y1 + 0.5f * h;
        float gw  = w - x1;      // faithful to source
        float gh  = h * y1;      // faithful to source
        gx1 = gxc - 0.5f * gw; gx2 = gxc + 0.5f * gw;
        gy1 = gyc - 0.5f * gh; gy2 = gyc + 0.5f * gh;
        s = gw * gh + 1e-9f;
        if (!v) { gx1 = INF; gx2 = -INF; gy1 = INF; gy2 = -INF; s = 1e-9f; }
    }

    // ---- IoU sweep: warp handles its 32 preds, lane = m ----
    // Within a lane, IEEE '>' keeps first index on +0/-0 ties (argmax parity);
    // -0.0 canonicalized once at key-pack time for the cross-warp merge.
    unsigned mask = 0;
    float best = -INF;
    int   bestj = 0;
    const int base = warp * 32;
    const int pw = tile * TILE + base;
    int jcnt = nrec - base;
    if (jcnt > 32) jcnt = 32;
    if (jcnt < 0)  jcnt = 0;

    if (jcnt == 32) {
        #pragma unroll
        for (int j = 0; j < 32; ++j) {
            float4 bx = sBox[base + j];       // broadcast LDS.128
            float  ap = sArea[base + j];      // broadcast LDS.32
            float dx = fmaxf(fminf(gx2, bx.x) - fmaxf(gx1, bx.z), 0.f);
            float dy = fmaxf(fminf(gy2, bx.y) - fmaxf(gy1, bx.w), 0.f);
            float inter = dx * dy;
            float iou = __fdividef(inter, (s + ap) - inter);
            if (iou > 0.6f) mask |= (1u << j);
            if (iou > best) { best = iou; bestj = j; }
        }
    } else {
        for (int j = 0; j < jcnt; ++j) {
            float4 bx = sBox[base + j];
            float  ap = sArea[base + j];
            float dx = fmaxf(fminf(gx2, bx.x) - fmaxf(gx1, bx.z), 0.f);
            float dy = fmaxf(fminf(gy2, bx.y) - fmaxf(gy1, bx.w), 0.f);
            float inter = dx * dy;
            float iou = __fdividef(inter, (s + ap) - inter);
            if (iou > 0.6f) mask |= (1u << j);
            if (iou > best) { best = iou; bestj = j; }
        }
    }
    unsigned objw = __reduce_or_sync(0xFFFFFFFFu, mask);  // bit j = obj(pred pw+j)
    bool myobj = (objw >> lane) & 1u;

    if (lane < MM) {
        if (__float_as_uint(best) == 0x80000000u) best = 0.0f;  // -0 -> +0
        unsigned long long pk =
            ((unsigned long long)okey(best) << 32) | (unsigned int)(~(pw + bestj));
        atomicMax(&sMerge[lane], pk);
    }

    // ---- conf partial reduce (fixed order -> deterministic) ----
    float acc = (tid < nrec) ? (myobj ? t1 : t2) : 0.f;
    #pragma unroll
    for (int o = 16; o; o >>= 1) acc += __shfl_down_sync(0xFFFFFFFFu, acc, o);
    if (lane == 0) sConf[warp] = acc;
    __syncthreads();

    // ---- warp 0 publishes this tile's results, then maybe runs the tail ----
    if (warp != 0) return;

    if (lane < MM) g_part[(size_t)blockIdx.x * MM + lane] = sMerge[lane];
    {
        float v = (lane < TILE / 32) ? sConf[lane] : 0.f;
        #pragma unroll
        for (int o = 4; o; o >>= 1) v += __shfl_down_sync(0xFFFFFFFFu, v, o);
        if (lane == 0) g_confp[blockIdx.x] = v;
    }
    __threadfence();
    __syncwarp();
    int cnt = 0;
    if (lane == 0) cnt = atomicAdd(&g_bctr[b], 1);
    cnt = __shfl_sync(0xFFFFFFFFu, cnt, 0);
    if (cnt != NTILES - 1) return;

    // ===== per-batch post (last-arriving tile-block of batch b) =====
    unsigned long long bk = 0ull;
    float x1 = 0.f, y1 = 0.f, w = 0.f, h = 0.f;
    bool valid = false;
    if (lane < MM) {
        x1 = sTgt[lane * 5 + 0]; y1 = sTgt[lane * 5 + 1];
        w  = sTgt[lane * 5 + 2]; h  = sTgt[lane * 5 + 3];
        valid = (sTgt[lane * 5 + 4] == 1.0f);
        #pragma unroll
        for (int k = 0; k < NTILES; ++k) {
            unsigned long long v = __ldcg(&g_part[((size_t)b * NTILES + k) * MM + lane]);
            if (v > bk) bk = v;
        }
    }
    int p = valid ? (int)(~(unsigned int)bk) : (0x10000 + lane);

    // scatter .set semantics: same flat index -> highest m (last write) wins
    unsigned grp = __match_any_sync(0xFFFFFFFFu, p);
    bool writer = valid && (lane == 31 - __clz(grp));

    float term = 0.f;
    if (writer) {
        int ra = p % AA, rw = (p / AA) % SS, rh = p / (AA * SS);
        float gxc = x1 + 0.5f * w;
        float gyc = y1 + 0.5f * h;
        float vx = (gxc - (float)rw * CWF) / CWF;
        float vy = (gyc - (float)rh * CWF) / CWF;
        float vw_ = logf((w / CWF) / __ldg(&anc[2 * ra]));
        float vh_ = logf((h / CWF) / __ldg(&anc[2 * ra + 1]));
        const float* pv = pred + ((size_t)b * PP + p) * 25;
        float p0 = 1.f   / (1.f + expf(-pv[0]));
        float p1 = 1.f   / (1.f + expf(-pv[1]));
        float p2 = 0.5f  / (1.f + expf(-pv[2]));
        float p3 = 0.5f  / (1.f + expf(-pv[3]));
        float d0 = p0 - vx, d1 = p1 - vy, d2 = p2 - vw_, d3 = p3 - vh_;
        term = d0 * d0 + d1 * d1 + d2 * d2 + d3 * d3;
    }
    float cpart = (lane < NTILES) ? __ldcg(&g_confp[b * NTILES + lane]) : 0.f;
    #pragma unroll
    for (int o = 16; o; o >>= 1) {
        term  += __shfl_down_sync(0xFFFFFFFFu, term,  o);
        cpart += __shfl_down_sync(0xFFFFFFFFu, cpart, o);
    }

    int done = 0;
    if (lane == 0) {
        g_bctr[b] = 0;                 // reset for next launch
        g_bloc[b]  = (double)term;
        g_bconf[b] = (double)cpart;
        __threadfence();
        done = atomicAdd(&g_gctr, 1);
    }
    done = __shfl_sync(0xFFFFFFFFu, done, 0);
    if (done != BB - 1) return;

    // ===== global finalize (deterministic fixed-order reduce) =====
    double l = 0.0, c = 0.0;
    for (int i = lane; i < BB; i += 32) {
        l += __ldcg(&g_bloc[i]);
        c += __ldcg(&g_bconf[i]);
    }
    #pragma unroll
    for (int o = 16; o; o >>= 1) {
        l += __shfl_down_sync(0xFFFFFFFFu, l, o);
        c += __shfl_down_sync(0xFFFFFFFFu, c, o);
    }
    if (lane == 0) {
        double loc  = 5.0 * l / (double)BB;
        double conf = c / (double)BB;
        out[0] = (float)(loc + conf);
        out[1] = (float)loc;
        out[2] = (float)conf;
        g_gctr = 0;                    // reset for next launch
    }
}

extern "C" void kernel_launch(void* const* d_in, const int* in_sizes, int n_in,
                              void* d_out, int out_size)
{
    const float* pred = 0;
    const float* tgt  = 0;
    const float* anc  = 0;
    for (int i = 0; i < n_in; ++i) {
        if (in_sizes[i] == N_PRED)      pred = (const float*)d_in[i];
        else if (in_sizes[i] == N_TGT)  tgt  = (const float*)d_in[i];
        else if (in_sizes[i] == N_ANC)  anc  = (const float*)d_in[i];
    }
    float* out = (float*)d_out;

    k_main<<<BB * NTILES, TILE>>>(pred, tgt, anc, out);
}